// round 2
// baseline (speedup 1.0000x reference)
#include <cuda_runtime.h>
#include <cuda_fp16.h>
#include <math.h>

// CapsuleLayer dynamic routing v2:
//  - compute u_hat ONCE (fused with iter-0 s partial sums), store fp16 (151MB)
//  - all later s-passes and agreement passes stream u_hat from HBM (memory-bound)
//  - softmax replaced by unnormalized exp weights + 1/sum folded into squash

#define BB 64
#define NN 2304
#define CC 32
#define OO 16
#define II 8
#define CO 512
#define WROW 4096     // C*O*I floats per n
#define NCHUNK 144    // k_uhat n-chunks
#define NPC 16        // NN / NCHUNK
#define BG 32
#define NBG 2
#define SCH 18        // streaming pass n-chunks (128 n each)
#define SNP 128

// scratch (static device globals; no runtime allocation)
__device__ __half g_u[(size_t)BB * NN * CO];          // 151 MB u_hat fp16
__device__ float  g_spart[(size_t)NCHUNK * BB * CO];  // 18.9 MB s partials
__device__ float  g_v[BB * CO];
__device__ float  g_bupd[8 * NN * CC];                // agreement partials per b-group
__device__ float  g_b[NN * CC];
__device__ float  g_e[NN * CC];                       // exp(b) (unnormalized c_ij)
__device__ float  g_epart[288 * CC];
__device__ float  g_inv[CC];                          // 1 / sum_n e

// ---------------------------------------------------------------------------
// k_uhat: compute t[b,n,co], store fp16 to g_u, accumulate iter-0 s partials
// (uniform weight). block = (n-chunk of 16, b-group of 32); 256 threads,
// thread owns co pair (2t, 2t+1).
// ---------------------------------------------------------------------------
__global__ __launch_bounds__(256, 2)
void k_uhat(const float* __restrict__ x, const float* __restrict__ W)
{
    const int chunk = blockIdx.x;
    const int bg    = blockIdx.y;
    const int t     = threadIdx.x;
    const int n0    = chunk * NPC;
    const int co0   = 2 * t;

    __shared__ float4 xs4[NPC * BG * 2];   // [nn][b][i4] 16KB

    const float4* x4 = (const float4*)x;
    for (int idx = t; idx < NPC * BG * 2; idx += 256) {
        int nn  = idx >> 6;
        int rem = idx & 63;
        int b   = rem >> 1;
        int i4  = rem & 1;
        xs4[idx] = x4[((size_t)(bg * BG + b) * NN + (n0 + nn)) * 2 + i4];
    }
    __syncthreads();

    float acc0[BG], acc1[BG];
#pragma unroll
    for (int b = 0; b < BG; b++) { acc0[b] = 0.0f; acc1[b] = 0.0f; }

    const float4* wbase = (const float4*)(W + (size_t)n0 * WROW + (size_t)co0 * II);
    // u row pointer: g_u[b][n][co] ; half2 granularity, co-pair index = t
    __half2* ubase = (__half2*)g_u + ((size_t)(bg * BG) * NN) * (CO / 2) + t;

    for (int nn = 0; nn < NPC; nn++) {
        const float4* wp = wbase + (size_t)nn * (WROW / 4);
        float4 wa0 = wp[0], wb0 = wp[1], wa1 = wp[2], wb1 = wp[3];
        float w0[8] = {wa0.x, wa0.y, wa0.z, wa0.w, wb0.x, wb0.y, wb0.z, wb0.w};
        float w1[8] = {wa1.x, wa1.y, wa1.z, wa1.w, wb1.x, wb1.y, wb1.z, wb1.w};
        const float4* xr = xs4 + nn * (BG * 2);
        __half2* up = ubase + (size_t)(n0 + nn) * (CO / 2);
#pragma unroll 8
        for (int b = 0; b < BG; b++) {
            float4 xa = xr[2 * b];
            float4 xb = xr[2 * b + 1];
            float t0 = w0[0] * xa.x;
            t0 = fmaf(w0[1], xa.y, t0); t0 = fmaf(w0[2], xa.z, t0);
            t0 = fmaf(w0[3], xa.w, t0); t0 = fmaf(w0[4], xb.x, t0);
            t0 = fmaf(w0[5], xb.y, t0); t0 = fmaf(w0[6], xb.z, t0);
            t0 = fmaf(w0[7], xb.w, t0);
            float t1 = w1[0] * xa.x;
            t1 = fmaf(w1[1], xa.y, t1); t1 = fmaf(w1[2], xa.z, t1);
            t1 = fmaf(w1[3], xa.w, t1); t1 = fmaf(w1[4], xb.x, t1);
            t1 = fmaf(w1[5], xb.y, t1); t1 = fmaf(w1[6], xb.z, t1);
            t1 = fmaf(w1[7], xb.w, t1);
            acc0[b] += t0; acc1[b] += t1;
            up[(size_t)b * NN * (CO / 2)] = __floats2half2_rn(t0, t1);
        }
    }

    float* spbase = g_spart + ((size_t)chunk * BB + (size_t)bg * BG) * CO + co0;
#pragma unroll
    for (int b = 0; b < BG; b++)
        *(float2*)(spbase + (size_t)b * CO) = make_float2(acc0[b], acc1[b]);
}

// ---------------------------------------------------------------------------
// k_s: s partials from stored u_hat, weighted by g_e.
// block = (n-chunk of 128, b). threads: nl = t>>6 (0..3), coct = t&63 (8 co).
// ---------------------------------------------------------------------------
__global__ __launch_bounds__(256)
void k_s()
{
    const int chunk = blockIdx.x;
    const int b     = blockIdx.y;
    const int t     = threadIdx.x;
    const int n0    = chunk * SNP;
    const int nl    = t >> 6;
    const int coct  = t & 63;
    const int c     = coct >> 1;

    __shared__ float es[SNP * CC];      // 16KB
    __shared__ float red[256][8];       // 8KB

    for (int idx = t; idx < SNP * CC; idx += 256)
        es[idx] = g_e[(size_t)(n0 + (idx >> 5)) * CC + (idx & 31)];
    __syncthreads();

    float acc[8];
#pragma unroll
    for (int k = 0; k < 8; k++) acc[k] = 0.0f;

    const float4* ub = (const float4*)g_u + ((size_t)b * NN + n0) * (CO / 8) + coct;

#pragma unroll 4
    for (int it = 0; it < SNP / 4; it++) {
        int nn = nl + it * 4;
        float w = es[nn * CC + c];
        float4 raw = ub[(size_t)nn * (CO / 8)];
        const __half2* h = (const __half2*)&raw;
#pragma unroll
        for (int k = 0; k < 4; k++) {
            float2 f = __half22float2(h[k]);
            acc[2 * k]     = fmaf(f.x, w, acc[2 * k]);
            acc[2 * k + 1] = fmaf(f.y, w, acc[2 * k + 1]);
        }
    }

#pragma unroll
    for (int k = 0; k < 8; k++) red[t][k] = acc[k];
    __syncthreads();
    if (nl == 0) {
        float out[8];
#pragma unroll
        for (int k = 0; k < 8; k++)
            out[k] = red[coct][k] + red[coct + 64][k] + red[coct + 128][k] + red[coct + 192][k];
        float* sp = g_spart + ((size_t)chunk * BB + b) * CO + coct * 8;
        *(float4*)sp       = make_float4(out[0], out[1], out[2], out[3]);
        *(float4*)(sp + 4) = make_float4(out[4], out[5], out[6], out[7]);
    }
}

// ---------------------------------------------------------------------------
// k_squash: reduce partials over nch chunks, scale by 1/sum_e (or 1/N if
// uniform), apply squash. writes g_v (and d_out on final pass).
// ---------------------------------------------------------------------------
__global__ void k_squash(float* __restrict__ dout, int nch, int uniform, int final_pass)
{
    int id = blockIdx.x * 256 + threadIdx.x;   // b*512 + co
    float s = 0.0f;
    for (int ch = 0; ch < nch; ch++)
        s += g_spart[(size_t)ch * (BB * CO) + id];
    int c = (id >> 4) & 31;
    float scale = uniform ? (1.0f / (float)NN) : g_inv[c];
    s *= scale;
    float vv = s * fabsf(s) / (1.0f + s * s);
    if (final_pass) dout[id] = vv;
    else            g_v[id]  = vv;
}

// ---------------------------------------------------------------------------
// k_agree: a partials. block = (n-chunk of 128, b-group of 8).
// thread: bl = t&3, coct = t>>2. segment of 8 threads covers one c.
// ---------------------------------------------------------------------------
__global__ __launch_bounds__(256)
void k_agree()
{
    const int chunk = blockIdx.x;
    const int bgi   = blockIdx.y;
    const int t     = threadIdx.x;
    const int n0    = chunk * SNP;
    const int bl    = t & 3;
    const int coct  = t >> 2;           // 0..63
    const int b0    = bgi * 8;

    // preload v for the 2 b-rows this thread handles
    float vr[2][8];
#pragma unroll
    for (int j = 0; j < 2; j++) {
        const float4* vp = (const float4*)(g_v + (size_t)(b0 + bl + 4 * j) * CO + coct * 8);
        float4 a = vp[0], bq = vp[1];
        vr[j][0] = a.x; vr[j][1] = a.y; vr[j][2] = a.z; vr[j][3] = a.w;
        vr[j][4] = bq.x; vr[j][5] = bq.y; vr[j][6] = bq.z; vr[j][7] = bq.w;
    }

    const float4* ub = (const float4*)g_u;

#pragma unroll 2
    for (int n = 0; n < SNP; n++) {
        float p = 0.0f;
#pragma unroll
        for (int j = 0; j < 2; j++) {
            int b = b0 + bl + 4 * j;
            float4 raw = ub[((size_t)b * NN + n0 + n) * (CO / 8) + coct];
            const __half2* h = (const __half2*)&raw;
#pragma unroll
            for (int k = 0; k < 4; k++) {
                float2 f = __half22float2(h[k]);
                p = fmaf(f.x, vr[j][2 * k],     p);
                p = fmaf(f.y, vr[j][2 * k + 1], p);
            }
        }
        p += __shfl_down_sync(0xffffffffu, p, 4, 8);
        p += __shfl_down_sync(0xffffffffu, p, 2, 8);
        p += __shfl_down_sync(0xffffffffu, p, 1, 8);
        if ((t & 7) == 0)
            g_bupd[(size_t)bgi * (NN * CC) + (size_t)(n0 + n) * CC + (t >> 3)] = p;
    }
}

// ---------------------------------------------------------------------------
// k_bcomb: combine 8 agreement partials, update b, e = exp(b),
// per-block partial e-sums per c. grid 288 x 256.
// ---------------------------------------------------------------------------
__global__ void k_bcomb(int iter0)
{
    const int t   = threadIdx.x;
    const int idx = blockIdx.x * 256 + t;     // n*32 + c
    const int c   = idx & 31;

    float a = 0.0f;
#pragma unroll
    for (int bg = 0; bg < 8; bg++)
        a += g_bupd[(size_t)bg * (NN * CC) + idx];
    a *= (1.0f / (float)BB);

    float bb = iter0 ? a : (g_b[idx] + a);
    g_b[idx] = bb;
    float e = expf(bb);
    g_e[idx] = e;

    __shared__ float sred[256];
    sred[t] = e;
    __syncthreads();
    if (t < 32) {
        float s = 0.0f;
#pragma unroll
        for (int r = 0; r < 8; r++) s += sred[r * 32 + t];
        g_epart[blockIdx.x * 32 + t] = s;
    }
}

// ---------------------------------------------------------------------------
// k_esum: per-c total of e, store reciprocal. grid 32 x 256.
// ---------------------------------------------------------------------------
__global__ void k_esum()
{
    const int c = blockIdx.x;
    const int t = threadIdx.x;
    __shared__ float red[256];
    float s = 0.0f;
    for (int i = t; i < 288; i += 256)
        s += g_epart[i * 32 + c];
    red[t] = s;
    __syncthreads();
    for (int off = 128; off > 0; off >>= 1) {
        if (t < off) red[t] += red[t + off];
        __syncthreads();
    }
    if (t == 0) g_inv[c] = 1.0f / red[0];
}

// ---------------------------------------------------------------------------
extern "C" void kernel_launch(void* const* d_in, const int* in_sizes, int n_in,
                              void* d_out, int out_size)
{
    const float* x = (const float*)d_in[0];   // [B, N, I]
    const float* W = (const float*)d_in[1];   // [N, C, O, I]
    float* out = (float*)d_out;               // [B, C, O, 1]

    dim3 gu(NCHUNK, NBG);
    dim3 gs(SCH, BB);
    dim3 ga(SCH, 8);

    // iteration 0: compute u_hat + uniform-weight s partials
    k_uhat<<<gu, 256>>>(x, W);
    k_squash<<<128, 256>>>(out, NCHUNK, 1, 0);
    k_agree<<<ga, 256>>>();
    k_bcomb<<<288, 256>>>(1);
    k_esum<<<32, 256>>>();

    // iteration 1
    k_s<<<gs, 256>>>();
    k_squash<<<128, 256>>>(out, SCH, 0, 0);
    k_agree<<<ga, 256>>>();
    k_bcomb<<<288, 256>>>(0);
    k_esum<<<32, 256>>>();

    // iteration 2 (final)
    k_s<<<gs, 256>>>();
    k_squash<<<128, 256>>>(out, SCH, 0, 1);
}

// round 3
// speedup vs baseline: 1.2590x; 1.2590x over previous
#include <cuda_runtime.h>
#include <math.h>

// CapsuleLayer dynamic routing v3: recompute u_hat each pass (no materialization),
// inner loops on packed fp32x2 FMA (fma.rn.f32x2, 2 FMA/issue on sm_100a).
// softmax replaced by unnormalized exp weights; 1/sum folded into squash.

#define BB 64
#define NN 2304
#define CC 32
#define OO 16
#define II 8
#define CO 512
#define WROW 4096     // C*O*I floats per n
#define NCHUNK 72
#define NPC 32        // NN / NCHUNK
#define BG 16         // batch rows per block
#define NBG 4

// scratch (static device globals; no runtime allocation)
__device__ float g_spart[(size_t)NCHUNK * BB * CO];  // 9.4 MB
__device__ float g_v[BB * CO];
__device__ float g_bupd[NBG * NN * CC];
__device__ float g_b[NN * CC];
__device__ float g_e[NN * CC];
__device__ float g_epart[288 * CC];
__device__ float g_inv[CC];

typedef unsigned long long u64;

__device__ __forceinline__ u64 pk2(float lo, float hi) {
    u64 r; asm("mov.b64 %0,{%1,%2};" : "=l"(r) : "f"(lo), "f"(hi)); return r;
}
__device__ __forceinline__ float2 unpk(u64 v) {
    float2 r; asm("mov.b64 {%0,%1},%2;" : "=f"(r.x), "=f"(r.y) : "l"(v)); return r;
}
__device__ __forceinline__ u64 ffma2(u64 a, u64 b, u64 c) {
    u64 d; asm("fma.rn.f32x2 %0,%1,%2,%3;" : "=l"(d) : "l"(a), "l"(b), "l"(c)); return d;
}
__device__ __forceinline__ u64 fmul2(u64 a, u64 b) {
    u64 d; asm("mul.rn.f32x2 %0,%1,%2;" : "=l"(d) : "l"(a), "l"(b)); return d;
}

// ---------------------------------------------------------------------------
// k_sj: s partials. block = (n-chunk of 32, b-group of 16); 256 threads.
// Thread owns co pair (2t,2t+1) packed in f32x2 lanes, 16 b accumulators.
// x tile pre-duplicated in smem: xs[ihp][b][nn] = ulonglong2{dup(x_i),dup(x_{i+1})}
// ---------------------------------------------------------------------------
__global__ __launch_bounds__(256, 2)
void k_sj(const float* __restrict__ x, const float* __restrict__ W, int use_e)
{
    const int chunk = blockIdx.x;
    const int bg    = blockIdx.y;
    const int t     = threadIdx.x;
    const int n0    = chunk * NPC;
    const int c     = t >> 3;

    __shared__ ulonglong2 xs[4 * BG * NPC];   // 32KB
    __shared__ float es[NPC * CC];            // 4KB

    const float4* x4 = (const float4*)x;
    for (int task = t; task < NPC * BG; task += 256) {
        int nn = task & (NPC - 1);
        int b  = task >> 5;
        const float4* xp = x4 + ((size_t)(bg * BG + b) * NN + (n0 + nn)) * 2;
        float4 g0 = xp[0], g1 = xp[1];
        xs[(0 * BG + b) * NPC + nn] = make_ulonglong2(pk2(g0.x, g0.x), pk2(g0.y, g0.y));
        xs[(1 * BG + b) * NPC + nn] = make_ulonglong2(pk2(g0.z, g0.z), pk2(g0.w, g0.w));
        xs[(2 * BG + b) * NPC + nn] = make_ulonglong2(pk2(g1.x, g1.x), pk2(g1.y, g1.y));
        xs[(3 * BG + b) * NPC + nn] = make_ulonglong2(pk2(g1.z, g1.z), pk2(g1.w, g1.w));
    }
    if (use_e) {
        for (int idx = t; idx < NPC * CC; idx += 256)
            es[idx] = g_e[(size_t)n0 * CC + idx];
    }
    __syncthreads();

    u64 acc[BG];
#pragma unroll
    for (int b = 0; b < BG; b++) acc[b] = 0ull;

    const float4* wp = (const float4*)(W + (size_t)n0 * WROW + (size_t)(2 * t) * II);
    float4 wa0 = wp[0], wa1 = wp[1], wb0 = wp[2], wb1 = wp[3];

    for (int nn = 0; nn < NPC; nn++) {
        float cw = use_e ? es[nn * CC + c] : (1.0f / (float)NN);
        u64 cwd = pk2(cw, cw);
        u64 pk[8];
        pk[0] = fmul2(pk2(wa0.x, wb0.x), cwd); pk[1] = fmul2(pk2(wa0.y, wb0.y), cwd);
        pk[2] = fmul2(pk2(wa0.z, wb0.z), cwd); pk[3] = fmul2(pk2(wa0.w, wb0.w), cwd);
        pk[4] = fmul2(pk2(wa1.x, wb1.x), cwd); pk[5] = fmul2(pk2(wa1.y, wb1.y), cwd);
        pk[6] = fmul2(pk2(wa1.z, wb1.z), cwd); pk[7] = fmul2(pk2(wa1.w, wb1.w), cwd);
        if (nn + 1 < NPC) {   // prefetch next n's W while computing
            const float4* wn = wp + (size_t)(nn + 1) * (WROW / 4);
            wa0 = wn[0]; wa1 = wn[1]; wb0 = wn[2]; wb1 = wn[3];
        }
        const ulonglong2* xr = xs + nn;
#pragma unroll
        for (int b = 0; b < BG; b++) {
            ulonglong2 x01 = xr[(0 * BG + b) * NPC];
            ulonglong2 x23 = xr[(1 * BG + b) * NPC];
            ulonglong2 x45 = xr[(2 * BG + b) * NPC];
            ulonglong2 x67 = xr[(3 * BG + b) * NPC];
            u64 a_ = acc[b];
            a_ = ffma2(pk[0], x01.x, a_); a_ = ffma2(pk[1], x01.y, a_);
            a_ = ffma2(pk[2], x23.x, a_); a_ = ffma2(pk[3], x23.y, a_);
            a_ = ffma2(pk[4], x45.x, a_); a_ = ffma2(pk[5], x45.y, a_);
            a_ = ffma2(pk[6], x67.x, a_); a_ = ffma2(pk[7], x67.y, a_);
            acc[b] = a_;
        }
    }

    float* sp = g_spart + ((size_t)chunk * BB + (size_t)bg * BG) * CO + 2 * t;
#pragma unroll
    for (int b = 0; b < BG; b++) {
        float2 v = unpk(acc[b]);
        *(float2*)(sp + (size_t)b * CO) = v;
    }
}

// ---------------------------------------------------------------------------
// k_bupd: agreement partials. Same tiling; per n recompute t, dot with v,
// shfl-reduce over the 8 threads (16 o) of each c.
// ---------------------------------------------------------------------------
__global__ __launch_bounds__(256, 2)
void k_bupd(const float* __restrict__ x, const float* __restrict__ W)
{
    const int chunk = blockIdx.x;
    const int bg    = blockIdx.y;
    const int t     = threadIdx.x;
    const int n0    = chunk * NPC;

    __shared__ ulonglong2 xs[4 * BG * NPC];   // 32KB

    const float4* x4 = (const float4*)x;
    for (int task = t; task < NPC * BG; task += 256) {
        int nn = task & (NPC - 1);
        int b  = task >> 5;
        const float4* xp = x4 + ((size_t)(bg * BG + b) * NN + (n0 + nn)) * 2;
        float4 g0 = xp[0], g1 = xp[1];
        xs[(0 * BG + b) * NPC + nn] = make_ulonglong2(pk2(g0.x, g0.x), pk2(g0.y, g0.y));
        xs[(1 * BG + b) * NPC + nn] = make_ulonglong2(pk2(g0.z, g0.z), pk2(g0.w, g0.w));
        xs[(2 * BG + b) * NPC + nn] = make_ulonglong2(pk2(g1.x, g1.x), pk2(g1.y, g1.y));
        xs[(3 * BG + b) * NPC + nn] = make_ulonglong2(pk2(g1.z, g1.z), pk2(g1.w, g1.w));
    }
    __syncthreads();

    u64 vp[BG];
#pragma unroll
    for (int b = 0; b < BG; b++) {
        float2 vv = *(const float2*)(g_v + (size_t)(bg * BG + b) * CO + 2 * t);
        vp[b] = pk2(vv.x, vv.y);
    }

    const float4* wp = (const float4*)(W + (size_t)n0 * WROW + (size_t)(2 * t) * II);
    float4 wa0 = wp[0], wa1 = wp[1], wb0 = wp[2], wb1 = wp[3];

    for (int nn = 0; nn < NPC; nn++) {
        u64 pk[8];
        pk[0] = pk2(wa0.x, wb0.x); pk[1] = pk2(wa0.y, wb0.y);
        pk[2] = pk2(wa0.z, wb0.z); pk[3] = pk2(wa0.w, wb0.w);
        pk[4] = pk2(wa1.x, wb1.x); pk[5] = pk2(wa1.y, wb1.y);
        pk[6] = pk2(wa1.z, wb1.z); pk[7] = pk2(wa1.w, wb1.w);
        if (nn + 1 < NPC) {
            const float4* wn = wp + (size_t)(nn + 1) * (WROW / 4);
            wa0 = wn[0]; wa1 = wn[1]; wb0 = wn[2]; wb1 = wn[3];
        }
        const ulonglong2* xr = xs + nn;
        u64 pacc = 0ull;
#pragma unroll
        for (int b = 0; b < BG; b++) {
            ulonglong2 x01 = xr[(0 * BG + b) * NPC];
            ulonglong2 x23 = xr[(1 * BG + b) * NPC];
            ulonglong2 x45 = xr[(2 * BG + b) * NPC];
            ulonglong2 x67 = xr[(3 * BG + b) * NPC];
            u64 tb = fmul2(pk[0], x01.x);
            tb = ffma2(pk[1], x01.y, tb);
            tb = ffma2(pk[2], x23.x, tb); tb = ffma2(pk[3], x23.y, tb);
            tb = ffma2(pk[4], x45.x, tb); tb = ffma2(pk[5], x45.y, tb);
            tb = ffma2(pk[6], x67.x, tb); tb = ffma2(pk[7], x67.y, tb);
            pacc = ffma2(tb, vp[b], pacc);
        }
        float2 pv = unpk(pacc);
        float p = pv.x + pv.y;
        p += __shfl_down_sync(0xffffffffu, p, 4, 8);
        p += __shfl_down_sync(0xffffffffu, p, 2, 8);
        p += __shfl_down_sync(0xffffffffu, p, 1, 8);
        if ((t & 7) == 0)
            g_bupd[(size_t)bg * (NN * CC) + (size_t)(n0 + nn) * CC + (t >> 3)] = p;
    }
}

// ---------------------------------------------------------------------------
// k_squash: reduce s partials over 72 chunks, scale (1/sum_e for weighted
// passes; weight 1/N already applied in uniform pass), squash.
// ---------------------------------------------------------------------------
__global__ void k_squash(float* __restrict__ dout, int uniform, int final_pass)
{
    int id = blockIdx.x * 256 + threadIdx.x;   // b*512 + co
    float s = 0.0f;
#pragma unroll 8
    for (int ch = 0; ch < NCHUNK; ch++)
        s += g_spart[(size_t)ch * (BB * CO) + id];
    int c = (id >> 4) & 31;
    float scale = uniform ? 1.0f : g_inv[c];
    s *= scale;
    float vv = s * fabsf(s) / (1.0f + s * s);
    if (final_pass) dout[id] = vv;
    else            g_v[id]  = vv;
}

// ---------------------------------------------------------------------------
// k_bcomb: combine 4 agreement partials, update b, e = exp(b), partial e-sums.
// ---------------------------------------------------------------------------
__global__ void k_bcomb(int iter0)
{
    const int t   = threadIdx.x;
    const int idx = blockIdx.x * 256 + t;     // n*32 + c

    float a = 0.0f;
#pragma unroll
    for (int bg = 0; bg < NBG; bg++)
        a += g_bupd[(size_t)bg * (NN * CC) + idx];
    a *= (1.0f / (float)BB);

    float bb = iter0 ? a : (g_b[idx] + a);
    g_b[idx] = bb;
    float e = expf(bb);
    g_e[idx] = e;

    __shared__ float sred[256];
    sred[t] = e;
    __syncthreads();
    if (t < 32) {
        float s = 0.0f;
#pragma unroll
        for (int r = 0; r < 8; r++) s += sred[r * 32 + t];
        g_epart[blockIdx.x * 32 + t] = s;
    }
}

// ---------------------------------------------------------------------------
// k_esum: per-c total of e, store reciprocal.
// ---------------------------------------------------------------------------
__global__ void k_esum()
{
    const int c = blockIdx.x;
    const int t = threadIdx.x;
    __shared__ float red[256];
    float s = 0.0f;
    for (int i = t; i < 288; i += 256)
        s += g_epart[i * 32 + c];
    red[t] = s;
    __syncthreads();
    for (int off = 128; off > 0; off >>= 1) {
        if (t < off) red[t] += red[t + off];
        __syncthreads();
    }
    if (t == 0) g_inv[c] = 1.0f / red[0];
}

// ---------------------------------------------------------------------------
extern "C" void kernel_launch(void* const* d_in, const int* in_sizes, int n_in,
                              void* d_out, int out_size)
{
    const float* x = (const float*)d_in[0];   // [B, N, I]
    const float* W = (const float*)d_in[1];   // [N, C, O, I]
    float* out = (float*)d_out;               // [B, C, O, 1]

    dim3 g(NCHUNK, NBG);

    // iteration 0 (uniform weights 1/N inside k_sj)
    k_sj<<<g, 256>>>(x, W, 0);
    k_squash<<<128, 256>>>(out, 1, 0);
    k_bupd<<<g, 256>>>(x, W);
    k_bcomb<<<288, 256>>>(1);
    k_esum<<<32, 256>>>();

    // iteration 1 (weights = exp(b), normalized in squash)
    k_sj<<<g, 256>>>(x, W, 1);
    k_squash<<<128, 256>>>(out, 0, 0);
    k_bupd<<<g, 256>>>(x, W);
    k_bcomb<<<288, 256>>>(0);
    k_esum<<<32, 256>>>();

    // iteration 2 (final)
    k_sj<<<g, 256>>>(x, W, 1);
    k_squash<<<128, 256>>>(out, 0, 1);
}

// round 4
// speedup vs baseline: 1.7182x; 1.3647x over previous
#include <cuda_runtime.h>
#include <math.h>

// CapsuleLayer dynamic routing v4: recompute u_hat each pass; f32x2 FMA with
// B-PAIR lane packing (x un-duplicated in smem -> half the LDS pressure of v3;
// W lane-duplicated in registers on the idle ALU pipe).

#define BB 64
#define NN 2304
#define CC 32
#define OO 16
#define II 8
#define CO 512
#define WROW 4096     // C*O*I floats per n
#define NCHUNK 72
#define NPC 32        // NN / NCHUNK
#define BG 16         // batch rows per block
#define BP 8          // b-pairs per block
#define NBG 4

__device__ float g_spart[(size_t)NCHUNK * BB * CO];  // 9.4 MB
__device__ float g_v[BB * CO];
__device__ float g_bupd[NBG * NN * CC];
__device__ float g_b[NN * CC];
__device__ float g_e[NN * CC];
__device__ float g_epart[288 * CC];
__device__ float g_inv[CC];

typedef unsigned long long u64;

__device__ __forceinline__ u64 pk2(float lo, float hi) {
    u64 r; asm("mov.b64 %0,{%1,%2};" : "=l"(r) : "f"(lo), "f"(hi)); return r;
}
__device__ __forceinline__ float2 unpk(u64 v) {
    float2 r; asm("mov.b64 {%0,%1},%2;" : "=f"(r.x), "=f"(r.y) : "l"(v)); return r;
}
__device__ __forceinline__ u64 ffma2(u64 a, u64 b, u64 c) {
    u64 d; asm("fma.rn.f32x2 %0,%1,%2,%3;" : "=l"(d) : "l"(a), "l"(b), "l"(c)); return d;
}
__device__ __forceinline__ u64 fmul2(u64 a, u64 b) {
    u64 d; asm("mul.rn.f32x2 %0,%1,%2;" : "=l"(d) : "l"(a), "l"(b)); return d;
}

// shared x tile: xs[ipair(4)][bp(8)][nn(32)] of ulonglong2 = 16KB
// xs[ip][bp][nn] = { (x[b0,2ip],x[b1,2ip]), (x[b0,2ip+1],x[b1,2ip+1]) }
#define XS_LOAD(xs, x4, bg, n0, t)                                              \
    {                                                                            \
        int bp = (t) >> 5;                                                       \
        int nn = (t) & 31;                                                       \
        const float4* xp0 = (x4) + ((size_t)((bg) * BG + 2 * bp) * NN + ((n0) + nn)) * 2; \
        const float4* xp1 = (x4) + ((size_t)((bg) * BG + 2 * bp + 1) * NN + ((n0) + nn)) * 2; \
        float4 a0 = xp0[0], a1 = xp0[1];                                         \
        float4 c0 = xp1[0], c1 = xp1[1];                                         \
        xs[0][bp][nn] = make_ulonglong2(pk2(a0.x, c0.x), pk2(a0.y, c0.y));       \
        xs[1][bp][nn] = make_ulonglong2(pk2(a0.z, c0.z), pk2(a0.w, c0.w));       \
        xs[2][bp][nn] = make_ulonglong2(pk2(a1.x, c1.x), pk2(a1.y, c1.y));       \
        xs[3][bp][nn] = make_ulonglong2(pk2(a1.z, c1.z), pk2(a1.w, c1.w));       \
    }

// ---------------------------------------------------------------------------
// k_sj: s partials. block = (n-chunk of 32, b-group of 16); 256 threads.
// Thread owns co pair (2t,2t+1); accumulators acc0/acc1[bp] hold b-pairs.
// ---------------------------------------------------------------------------
__global__ __launch_bounds__(256, 2)
void k_sj(const float* __restrict__ x, const float* __restrict__ W, int use_e)
{
    const int chunk = blockIdx.x;
    const int bg    = blockIdx.y;
    const int t     = threadIdx.x;
    const int n0    = chunk * NPC;
    const int c     = t >> 3;

    __shared__ ulonglong2 xs[4][BP][NPC];   // 16KB
    __shared__ float es[NPC * CC];          // 4KB

    const float4* x4 = (const float4*)x;
    XS_LOAD(xs, x4, bg, n0, t);
    if (use_e) {
        for (int idx = t; idx < NPC * CC; idx += 256)
            es[idx] = g_e[(size_t)n0 * CC + idx];
    }
    __syncthreads();

    u64 acc0[BP], acc1[BP];
#pragma unroll
    for (int bp = 0; bp < BP; bp++) { acc0[bp] = 0ull; acc1[bp] = 0ull; }

    const float4* wp = (const float4*)(W + (size_t)n0 * WROW + (size_t)(2 * t) * II);
    float4 wa0 = wp[0], wa1 = wp[1], wb0 = wp[2], wb1 = wp[3];

    for (int nn = 0; nn < NPC; nn++) {
        float cw = use_e ? es[nn * CC + c] : (1.0f / (float)NN);
        u64 wc0[8], wc1[8];
        {
            float m;
            m = wa0.x * cw; wc0[0] = pk2(m, m);
            m = wa0.y * cw; wc0[1] = pk2(m, m);
            m = wa0.z * cw; wc0[2] = pk2(m, m);
            m = wa0.w * cw; wc0[3] = pk2(m, m);
            m = wa1.x * cw; wc0[4] = pk2(m, m);
            m = wa1.y * cw; wc0[5] = pk2(m, m);
            m = wa1.z * cw; wc0[6] = pk2(m, m);
            m = wa1.w * cw; wc0[7] = pk2(m, m);
            m = wb0.x * cw; wc1[0] = pk2(m, m);
            m = wb0.y * cw; wc1[1] = pk2(m, m);
            m = wb0.z * cw; wc1[2] = pk2(m, m);
            m = wb0.w * cw; wc1[3] = pk2(m, m);
            m = wb1.x * cw; wc1[4] = pk2(m, m);
            m = wb1.y * cw; wc1[5] = pk2(m, m);
            m = wb1.z * cw; wc1[6] = pk2(m, m);
            m = wb1.w * cw; wc1[7] = pk2(m, m);
        }
        if (nn + 1 < NPC) {
            const float4* wn = wp + (size_t)(nn + 1) * (WROW / 4);
            wa0 = wn[0]; wa1 = wn[1]; wb0 = wn[2]; wb1 = wn[3];
        }
#pragma unroll
        for (int bp = 0; bp < BP; bp++) {
            ulonglong2 x01 = xs[0][bp][nn];
            ulonglong2 x23 = xs[1][bp][nn];
            ulonglong2 x45 = xs[2][bp][nn];
            ulonglong2 x67 = xs[3][bp][nn];
            u64 a0 = acc0[bp], a1 = acc1[bp];
            a0 = ffma2(wc0[0], x01.x, a0); a0 = ffma2(wc0[1], x01.y, a0);
            a0 = ffma2(wc0[2], x23.x, a0); a0 = ffma2(wc0[3], x23.y, a0);
            a0 = ffma2(wc0[4], x45.x, a0); a0 = ffma2(wc0[5], x45.y, a0);
            a0 = ffma2(wc0[6], x67.x, a0); a0 = ffma2(wc0[7], x67.y, a0);
            a1 = ffma2(wc1[0], x01.x, a1); a1 = ffma2(wc1[1], x01.y, a1);
            a1 = ffma2(wc1[2], x23.x, a1); a1 = ffma2(wc1[3], x23.y, a1);
            a1 = ffma2(wc1[4], x45.x, a1); a1 = ffma2(wc1[5], x45.y, a1);
            a1 = ffma2(wc1[6], x67.x, a1); a1 = ffma2(wc1[7], x67.y, a1);
            acc0[bp] = a0; acc1[bp] = a1;
        }
    }

    // store: lanes of acc hold (b_even, b_odd); emit [b][co] float2 rows
    float* sp = g_spart + ((size_t)chunk * BB + (size_t)bg * BG) * CO + 2 * t;
#pragma unroll
    for (int bp = 0; bp < BP; bp++) {
        float2 f0 = unpk(acc0[bp]);   // (s[b0,co0], s[b1,co0])
        float2 f1 = unpk(acc1[bp]);   // (s[b0,co1], s[b1,co1])
        *(float2*)(sp + (size_t)(2 * bp) * CO)     = make_float2(f0.x, f1.x);
        *(float2*)(sp + (size_t)(2 * bp + 1) * CO) = make_float2(f0.y, f1.y);
    }
}

// ---------------------------------------------------------------------------
// k_bupd: agreement partials; recompute t per n, dot with v (b-pair packed),
// shfl-reduce over the 8 threads (16 o) of each c.
// ---------------------------------------------------------------------------
__global__ __launch_bounds__(256, 2)
void k_bupd(const float* __restrict__ x, const float* __restrict__ W)
{
    const int chunk = blockIdx.x;
    const int bg    = blockIdx.y;
    const int t     = threadIdx.x;
    const int n0    = chunk * NPC;

    __shared__ ulonglong2 xs[4][BP][NPC];   // 16KB

    const float4* x4 = (const float4*)x;
    XS_LOAD(xs, x4, bg, n0, t);
    __syncthreads();

    // v packed over b-pairs for this thread's two co's
    u64 vp0[BP], vp1[BP];
#pragma unroll
    for (int bp = 0; bp < BP; bp++) {
        const float* v0 = g_v + (size_t)(bg * BG + 2 * bp) * CO + 2 * t;
        const float* v1 = g_v + (size_t)(bg * BG + 2 * bp + 1) * CO + 2 * t;
        float2 a = *(const float2*)v0;   // (v[b0,co0], v[b0,co1])
        float2 b = *(const float2*)v1;
        vp0[bp] = pk2(a.x, b.x);
        vp1[bp] = pk2(a.y, b.y);
    }

    const float4* wp = (const float4*)(W + (size_t)n0 * WROW + (size_t)(2 * t) * II);
    float4 wa0 = wp[0], wa1 = wp[1], wb0 = wp[2], wb1 = wp[3];

    for (int nn = 0; nn < NPC; nn++) {
        u64 wd0[8], wd1[8];
        wd0[0] = pk2(wa0.x, wa0.x); wd0[1] = pk2(wa0.y, wa0.y);
        wd0[2] = pk2(wa0.z, wa0.z); wd0[3] = pk2(wa0.w, wa0.w);
        wd0[4] = pk2(wa1.x, wa1.x); wd0[5] = pk2(wa1.y, wa1.y);
        wd0[6] = pk2(wa1.z, wa1.z); wd0[7] = pk2(wa1.w, wa1.w);
        wd1[0] = pk2(wb0.x, wb0.x); wd1[1] = pk2(wb0.y, wb0.y);
        wd1[2] = pk2(wb0.z, wb0.z); wd1[3] = pk2(wb0.w, wb0.w);
        wd1[4] = pk2(wb1.x, wb1.x); wd1[5] = pk2(wb1.y, wb1.y);
        wd1[6] = pk2(wb1.z, wb1.z); wd1[7] = pk2(wb1.w, wb1.w);
        if (nn + 1 < NPC) {
            const float4* wn = wp + (size_t)(nn + 1) * (WROW / 4);
            wa0 = wn[0]; wa1 = wn[1]; wb0 = wn[2]; wb1 = wn[3];
        }
        u64 pacc = 0ull;
#pragma unroll
        for (int bp = 0; bp < BP; bp++) {
            ulonglong2 x01 = xs[0][bp][nn];
            ulonglong2 x23 = xs[1][bp][nn];
            ulonglong2 x45 = xs[2][bp][nn];
            ulonglong2 x67 = xs[3][bp][nn];
            u64 t0 = fmul2(wd0[0], x01.x);
            t0 = ffma2(wd0[1], x01.y, t0);
            t0 = ffma2(wd0[2], x23.x, t0); t0 = ffma2(wd0[3], x23.y, t0);
            t0 = ffma2(wd0[4], x45.x, t0); t0 = ffma2(wd0[5], x45.y, t0);
            t0 = ffma2(wd0[6], x67.x, t0); t0 = ffma2(wd0[7], x67.y, t0);
            u64 t1 = fmul2(wd1[0], x01.x);
            t1 = ffma2(wd1[1], x01.y, t1);
            t1 = ffma2(wd1[2], x23.x, t1); t1 = ffma2(wd1[3], x23.y, t1);
            t1 = ffma2(wd1[4], x45.x, t1); t1 = ffma2(wd1[5], x45.y, t1);
            t1 = ffma2(wd1[6], x67.x, t1); t1 = ffma2(wd1[7], x67.y, t1);
            // lanes hold (t[b0], t[b1]); vp lanes hold (v[b0,co0], v[b1?]...)
            // NOTE: vp0 packs (v[b0,co0], v[b1,co0])? see load above: vp0 =
            // (v[b0,co0], v[b1,co0]) must pair with t0 lanes (b0,b1) of co0.
            pacc = ffma2(t0, vp0[bp], pacc);
            pacc = ffma2(t1, vp1[bp], pacc);
        }
        float2 pv = unpk(pacc);
        float p = pv.x + pv.y;
        p += __shfl_down_sync(0xffffffffu, p, 4, 8);
        p += __shfl_down_sync(0xffffffffu, p, 2, 8);
        p += __shfl_down_sync(0xffffffffu, p, 1, 8);
        if ((t & 7) == 0)
            g_bupd[(size_t)bg * (NN * CC) + (size_t)(n0 + nn) * CC + (t >> 3)] = p;
    }
}

// ---------------------------------------------------------------------------
__global__ void k_squash(float* __restrict__ dout, int uniform, int final_pass)
{
    int id = blockIdx.x * 256 + threadIdx.x;   // b*512 + co
    float s = 0.0f;
#pragma unroll 8
    for (int ch = 0; ch < NCHUNK; ch++)
        s += g_spart[(size_t)ch * (BB * CO) + id];
    int c = (id >> 4) & 31;
    float scale = uniform ? 1.0f : g_inv[c];
    s *= scale;
    float vv = s * fabsf(s) / (1.0f + s * s);
    if (final_pass) dout[id] = vv;
    else            g_v[id]  = vv;
}

// ---------------------------------------------------------------------------
__global__ void k_bcomb(int iter0)
{
    const int t   = threadIdx.x;
    const int idx = blockIdx.x * 256 + t;     // n*32 + c

    float a = 0.0f;
#pragma unroll
    for (int bg = 0; bg < NBG; bg++)
        a += g_bupd[(size_t)bg * (NN * CC) + idx];
    a *= (1.0f / (float)BB);

    float bb = iter0 ? a : (g_b[idx] + a);
    g_b[idx] = bb;
    float e = expf(bb);
    g_e[idx] = e;

    __shared__ float sred[256];
    sred[t] = e;
    __syncthreads();
    if (t < 32) {
        float s = 0.0f;
#pragma unroll
        for (int r = 0; r < 8; r++) s += sred[r * 32 + t];
        g_epart[blockIdx.x * 32 + t] = s;
    }
}

// ---------------------------------------------------------------------------
__global__ void k_esum()
{
    const int c = blockIdx.x;
    const int t = threadIdx.x;
    __shared__ float red[256];
    float s = 0.0f;
    for (int i = t; i < 288; i += 256)
        s += g_epart[i * 32 + c];
    red[t] = s;
    __syncthreads();
    for (int off = 128; off > 0; off >>= 1) {
        if (t < off) red[t] += red[t + off];
        __syncthreads();
    }
    if (t == 0) g_inv[c] = 1.0f / red[0];
}

// ---------------------------------------------------------------------------
extern "C" void kernel_launch(void* const* d_in, const int* in_sizes, int n_in,
                              void* d_out, int out_size)
{
    const float* x = (const float*)d_in[0];   // [B, N, I]
    const float* W = (const float*)d_in[1];   // [N, C, O, I]
    float* out = (float*)d_out;               // [B, C, O, 1]

    dim3 g(NCHUNK, NBG);

    // iteration 0 (uniform weights 1/N inside k_sj)
    k_sj<<<g, 256>>>(x, W, 0);
    k_squash<<<128, 256>>>(out, 1, 0);
    k_bupd<<<g, 256>>>(x, W);
    k_bcomb<<<288, 256>>>(1);
    k_esum<<<32, 256>>>();

    // iteration 1 (weights = exp(b), normalized in squash)
    k_sj<<<g, 256>>>(x, W, 1);
    k_squash<<<128, 256>>>(out, 0, 0);
    k_bupd<<<g, 256>>>(x, W);
    k_bcomb<<<288, 256>>>(0);
    k_esum<<<32, 256>>>();

    // iteration 2 (final)
    k_sj<<<g, 256>>>(x, W, 1);
    k_squash<<<128, 256>>>(out, 0, 1);
}